// round 13
// baseline (speedup 1.0000x reference)
#include <cuda_runtime.h>
#include <cuda_fp16.h>
#include <cstdint>

#define Bq   8
#define Sq   1024
#define HIDq 1024
#define NHq  16
#define HDq  64
#define Mq   (Bq * Sq)   // 8192

// Scratch (device globals: allocation-free per harness rules)
__device__ __half g_xh[(size_t)Mq * HIDq];     // A operand fp16 [M,K] (x, later ctx)
__device__ __half g_wt4[(size_t)4 * HIDq * HIDq];  // W^T fp16 [4][N,K] (q,k,v,p)
__device__ __half g_qh[(size_t)Bq * NHq * Sq * HDq];  // [B,NH,S,HD] (pre-scaled)
__device__ __half g_kh[(size_t)Bq * NHq * Sq * HDq];
__device__ __half g_vh[(size_t)Bq * NHq * Sq * HDq];

// ===========================================================================
// PTX helpers (portable tensor ISA: ldmatrix + mma.sync, sm_80+)
// ===========================================================================
__device__ __forceinline__ uint32_t smem_to_u32(const void* p) {
    uint32_t a;
    asm("{ .reg .u64 t; cvta.to.shared.u64 t, %1; cvt.u32.u64 %0, t; }"
        : "=r"(a) : "l"(p));
    return a;
}

#define LDMX4(r, addr) \
    asm volatile("ldmatrix.sync.aligned.m8n8.x4.shared.b16 {%0,%1,%2,%3}, [%4];" \
        : "=r"((r)[0]), "=r"((r)[1]), "=r"((r)[2]), "=r"((r)[3]) : "r"(addr))

#define LDMX2(r, addr) \
    asm volatile("ldmatrix.sync.aligned.m8n8.x2.shared.b16 {%0,%1}, [%2];" \
        : "=r"((r)[0]), "=r"((r)[1]) : "r"(addr))

#define LDMX2T(r, addr) \
    asm volatile("ldmatrix.sync.aligned.m8n8.x2.trans.shared.b16 {%0,%1}, [%2];" \
        : "=r"((r)[0]), "=r"((r)[1]) : "r"(addr))

#define MMA_F16(d, a, b) \
    asm volatile("mma.sync.aligned.m16n8k16.row.col.f32.f16.f16.f32 " \
        "{%0,%1,%2,%3}, {%4,%5,%6,%7}, {%8,%9}, {%0,%1,%2,%3};" \
        : "+f"((d)[0]), "+f"((d)[1]), "+f"((d)[2]), "+f"((d)[3]) \
        : "r"((a)[0]), "r"((a)[1]), "r"((a)[2]), "r"((a)[3]), \
          "r"((b)[0]), "r"((b)[1]))

#define CP_ASYNC16(smem, gmem) \
    asm volatile("cp.async.cg.shared.global [%0], [%1], 16;" \
        :: "r"(smem), "l"(gmem) : "memory")
#define CP_COMMIT()  asm volatile("cp.async.commit_group;" ::: "memory")
#define CP_WAIT(n)   asm volatile("cp.async.wait_group %0;" :: "n"(n) : "memory")

// ===========================================================================
// Conversion: x fp32 -> fp16
// ===========================================================================
__global__ __launch_bounds__(256) void convert_x_kernel(const float* __restrict__ src)
{
    const size_t i = ((size_t)blockIdx.x * 256 + threadIdx.x) * 8;
    float4 v0 = *(const float4*)(src + i);
    float4 v1 = *(const float4*)(src + i + 4);
    __half2 h0 = __floats2half2_rn(v0.x, v0.y);
    __half2 h1 = __floats2half2_rn(v0.z, v0.w);
    __half2 h2 = __floats2half2_rn(v1.x, v1.y);
    __half2 h3 = __floats2half2_rn(v1.z, v1.w);
    *(uint4*)(g_xh + i) = make_uint4(*(uint32_t*)&h0, *(uint32_t*)&h1,
                                     *(uint32_t*)&h2, *(uint32_t*)&h3);
}

// ===========================================================================
// All-weights transpose: g_wt4[z][n][k] = fp16(Wz[k][n]) for z in {q,k,v,p}
// ===========================================================================
__global__ __launch_bounds__(256) void convw_all_kernel(
    const float* __restrict__ W0, const float* __restrict__ W1,
    const float* __restrict__ W2, const float* __restrict__ W3)
{
    __shared__ float tile[32][33];
    const float* W = (blockIdx.z == 0) ? W0 : (blockIdx.z == 1) ? W1
                   : (blockIdx.z == 2) ? W2 : W3;
    __half* dst = g_wt4 + (size_t)blockIdx.z * HIDq * HIDq;
    const int bx = blockIdx.x * 32, by = blockIdx.y * 32;
    const int tx = threadIdx.x & 31, ty = threadIdx.x >> 5;  // 32 x 8
#pragma unroll
    for (int i = 0; i < 4; i++)
        tile[ty + i * 8][tx] = W[(size_t)(by + ty + i * 8) * HIDq + bx + tx];
    __syncthreads();
#pragma unroll
    for (int i = 0; i < 4; i++)
        dst[(size_t)(bx + ty + i * 8) * HIDq + by + tx] =
            __float2half(tile[tx][ty + i * 8]);
}

// ===========================================================================
// fp16 mma.sync GEMM core (R10-proven). KCH=64 (16 chunks), 2-stage cp.async.
// CTA 128x128, 8 warps (2m x 4n). Row stride 144 B (conflict-free).
// ===========================================================================
#define KCH    64
#define GTILE  18432                    // 128 rows x 144 B
#define GSTG   (2 * GTILE)              // A + B per stage
#define GSMEM  (2 * GSTG)               // 73728 B, 2 stages

// QKV merged GEMM: z = blockIdx.z selects weight slot, bias, destination.
__global__ __launch_bounds__(256, 2) void gemm_qkv_kernel(
    const float* __restrict__ b0, const float* __restrict__ b1,
    const float* __restrict__ b2)
{
    extern __shared__ char sm[];
    const uint32_t sb = smem_to_u32(sm);
    const int z = blockIdx.z;
    const __half* Wt = g_wt4 + (size_t)z * HIDq * HIDq;
    const float* bias = (z == 0) ? b0 : (z == 1) ? b1 : b2;
    __half* dst = (z == 0) ? g_qh : (z == 1) ? g_kh : g_vh;

    const int tid = threadIdx.x, lane = tid & 31, wid = tid >> 5;
    const int wm = wid >> 2, wn = wid & 3;
    const int bm = blockIdx.y * 128, bn = blockIdx.x * 128;

    float acc[4][4][4];
#pragma unroll
    for (int mi = 0; mi < 4; mi++)
#pragma unroll
        for (int ni = 0; ni < 4; ni++)
#pragma unroll
            for (int r = 0; r < 4; r++) acc[mi][ni][r] = 0.f;

    auto issue = [&](int c) {
        const uint32_t base = sb + (uint32_t)(c & 1) * GSTG;
        const int k0 = c * KCH;
#pragma unroll
        for (int t = 0; t < 4; t++) {
            const int id = t * 256 + tid;
            const int row = id >> 3, seg = id & 7;
            const uint32_t so = (uint32_t)row * 144 + seg * 16;
            CP_ASYNC16(base + so,         g_xh + (size_t)(bm + row) * HIDq + k0 + seg * 8);
            CP_ASYNC16(base + GTILE + so, Wt   + (size_t)(bn + row) * HIDq + k0 + seg * 8);
        }
        CP_COMMIT();
    };

    issue(0);

    for (int c = 0; c < HIDq / KCH; c++) {
        if (c + 1 < HIDq / KCH) { issue(c + 1); CP_WAIT(1); }
        else                    { CP_WAIT(0); }
        __syncthreads();

        const uint32_t base = sb + (uint32_t)(c & 1) * GSTG;

#pragma unroll
        for (int kk = 0; kk < KCH; kk += 16) {
            uint32_t bh[4][2];
#pragma unroll
            for (int ni = 0; ni < 4; ni++) {
                const uint32_t baddr = base + GTILE
                    + (uint32_t)(wn * 32 + ni * 8 + (lane & 7)) * 144
                    + (uint32_t)(kk + ((lane >> 3) & 1) * 8) * 2;
                LDMX2(bh[ni], baddr);
            }
#pragma unroll
            for (int mi = 0; mi < 4; mi++) {
                const uint32_t aaddr = base
                    + (uint32_t)(wm * 64 + mi * 16 + (lane & 15)) * 144
                    + (uint32_t)(kk + (lane >> 4) * 8) * 2;
                uint32_t ah[4];
                LDMX4(ah, aaddr);
#pragma unroll
                for (int ni = 0; ni < 4; ni++)
                    MMA_F16(acc[mi][ni], ah, bh[ni]);
            }
        }
        __syncthreads();
    }

    const int rbase = bm + wm * 64 + (lane >> 2);
    const int cbase = bn + wn * 32 + (lane & 3) * 2;
    const float qs = (z == 0) ? 0.03125f : 1.0f;
#pragma unroll
    for (int mi = 0; mi < 4; mi++) {
#pragma unroll
        for (int ni = 0; ni < 4; ni++) {
            const int col = cbase + ni * 8;
            const float2 b2v = *(const float2*)(bias + col);
#pragma unroll
            for (int half = 0; half < 2; half++) {
                const int row = rbase + mi * 16 + half * 8;
                const float ox = (acc[mi][ni][half * 2 + 0] + b2v.x) * qs;
                const float oy = (acc[mi][ni][half * 2 + 1] + b2v.y) * qs;
                const int b = row >> 10, s = row & 1023;
                const int h = col >> 6,  d = col & 63;
                const size_t off = (((size_t)(b * NHq + h)) * Sq + s) * HDq + d;
                __half2 h2 = __floats2half2_rn(ox, oy);
                *(uint32_t*)(dst + off) = *(uint32_t*)&h2;
            }
        }
    }
}

// Output projection: A = g_xh (ctx), W slot 3, fp32 row-major to d_out.
__global__ __launch_bounds__(256, 2) void gemm_out_kernel(
    const float* __restrict__ bias, float* __restrict__ Cout)
{
    extern __shared__ char sm[];
    const uint32_t sb = smem_to_u32(sm);
    const __half* Wt = g_wt4 + (size_t)3 * HIDq * HIDq;

    const int tid = threadIdx.x, lane = tid & 31, wid = tid >> 5;
    const int wm = wid >> 2, wn = wid & 3;
    const int bm = blockIdx.y * 128, bn = blockIdx.x * 128;

    float acc[4][4][4];
#pragma unroll
    for (int mi = 0; mi < 4; mi++)
#pragma unroll
        for (int ni = 0; ni < 4; ni++)
#pragma unroll
            for (int r = 0; r < 4; r++) acc[mi][ni][r] = 0.f;

    auto issue = [&](int c) {
        const uint32_t base = sb + (uint32_t)(c & 1) * GSTG;
        const int k0 = c * KCH;
#pragma unroll
        for (int t = 0; t < 4; t++) {
            const int id = t * 256 + tid;
            const int row = id >> 3, seg = id & 7;
            const uint32_t so = (uint32_t)row * 144 + seg * 16;
            CP_ASYNC16(base + so,         g_xh + (size_t)(bm + row) * HIDq + k0 + seg * 8);
            CP_ASYNC16(base + GTILE + so, Wt   + (size_t)(bn + row) * HIDq + k0 + seg * 8);
        }
        CP_COMMIT();
    };

    issue(0);

    for (int c = 0; c < HIDq / KCH; c++) {
        if (c + 1 < HIDq / KCH) { issue(c + 1); CP_WAIT(1); }
        else                    { CP_WAIT(0); }
        __syncthreads();

        const uint32_t base = sb + (uint32_t)(c & 1) * GSTG;

#pragma unroll
        for (int kk = 0; kk < KCH; kk += 16) {
            uint32_t bh[4][2];
#pragma unroll
            for (int ni = 0; ni < 4; ni++) {
                const uint32_t baddr = base + GTILE
                    + (uint32_t)(wn * 32 + ni * 8 + (lane & 7)) * 144
                    + (uint32_t)(kk + ((lane >> 3) & 1) * 8) * 2;
                LDMX2(bh[ni], baddr);
            }
#pragma unroll
            for (int mi = 0; mi < 4; mi++) {
                const uint32_t aaddr = base
                    + (uint32_t)(wm * 64 + mi * 16 + (lane & 15)) * 144
                    + (uint32_t)(kk + (lane >> 4) * 8) * 2;
                uint32_t ah[4];
                LDMX4(ah, aaddr);
#pragma unroll
                for (int ni = 0; ni < 4; ni++)
                    MMA_F16(acc[mi][ni], ah, bh[ni]);
            }
        }
        __syncthreads();
    }

    const int rbase = bm + wm * 64 + (lane >> 2);
    const int cbase = bn + wn * 32 + (lane & 3) * 2;
#pragma unroll
    for (int mi = 0; mi < 4; mi++) {
#pragma unroll
        for (int ni = 0; ni < 4; ni++) {
            const int col = cbase + ni * 8;
            const float2 b2v = *(const float2*)(bias + col);
#pragma unroll
            for (int half = 0; half < 2; half++) {
                const int row = rbase + mi * 16 + half * 8;
                *(float2*)(Cout + (size_t)row * HIDq + col) =
                    make_float2(acc[mi][ni][half * 2 + 0] + b2v.x,
                                acc[mi][ni][half * 2 + 1] + b2v.y);
            }
        }
    }
}

// ===========================================================================
// fp16 flash attention v3: 256 threads = 8 warps, warp owns 32 query rows
// (2 m-tiles) -> 256-query CTA tile, ONE CTA/SM (reg budget 255, ~160 used).
// Each K/V fragment feeds both m-tiles (halves K/V smem reads per query).
// ah and pf kept transient to avoid R11's spill. 64-key stages, 2-stage.
// ctx -> fp16 into g_xh [B*S, HID].
// ===========================================================================
#define QTILE  36864                    // 256 rows x 144 B
#define KVTILE 9216                     // 64 rows x 144 B
#define KVSTG  (2 * KVTILE)             // Kh, Vh
#define KVOFF  QTILE
#define ASMEM  (KVOFF + 2 * KVSTG)      // 73728
#define NTK    (Sq / 64)                // 16

__global__ __launch_bounds__(256, 1) void attn_mma_kernel(const float* __restrict__ mask)
{
    extern __shared__ char sm[];
    const uint32_t sb = smem_to_u32(sm);

    const int bh = blockIdx.y;
    const int b = bh >> 4, h = bh & 15;
    const int qbase = blockIdx.x * 256;
    const int tid = threadIdx.x, lane = tid & 31, wid = tid >> 5;
    const int wrow = wid * 32;

    const size_t hb = (size_t)bh * Sq * HDq;
    const __half* Qg = g_qh + hb;
    const __half* KVg[2] = {g_kh + hb, g_vh + hb};

    // Q load: 256 rows x 8 segs = 2048 segs / 256 thr = 8 each
#pragma unroll
    for (int t = 0; t < 8; t++) {
        const int id = t * 256 + tid;
        const int row = id >> 3, seg = id & 7;
        CP_ASYNC16(sb + (uint32_t)row * 144 + seg * 16,
                   Qg + (size_t)(qbase + row) * HDq + seg * 8);
    }

    auto issue_kv = [&](int kt) {
        const uint32_t base = sb + KVOFF + (uint32_t)(kt & 1) * KVSTG;
#pragma unroll
        for (int t = 0; t < 4; t++) {
            const int which = t >> 1;           // 0=Kh, 1=Vh
            const int id = (t & 1) * 256 + tid;
            const int row = id >> 3, seg = id & 7;
            CP_ASYNC16(base + (uint32_t)which * KVTILE + (uint32_t)row * 144 + seg * 16,
                       KVg[which] + (size_t)(kt * 64 + row) * HDq + seg * 8);
        }
        CP_COMMIT();
    };

    issue_kv(0);

    float m_st[2][2], l_st[2][2];
    float ctx[2][8][4];
#pragma unroll
    for (int mi = 0; mi < 2; mi++) {
        m_st[mi][0] = m_st[mi][1] = -1e30f;
        l_st[mi][0] = l_st[mi][1] = 0.f;
#pragma unroll
        for (int n = 0; n < 8; n++)
#pragma unroll
            for (int r = 0; r < 4; r++) ctx[mi][n][r] = 0.f;
    }

    for (int kt = 0; kt < NTK; kt++) {
        if (kt + 1 < NTK) { issue_kv(kt + 1); CP_WAIT(1); }
        else              { CP_WAIT(0); }
        __syncthreads();

        const uint32_t kvb = sb + KVOFF + (uint32_t)(kt & 1) * KVSTG;

        // ---- scores: K fragments shared by both m-tiles ----
        float accs[2][8][4];
#pragma unroll
        for (int mi = 0; mi < 2; mi++)
#pragma unroll
            for (int n = 0; n < 8; n++)
#pragma unroll
                for (int r = 0; r < 4; r++) accs[mi][n][r] = 0.f;

#pragma unroll
        for (int kq = 0; kq < 4; kq++) {
            uint32_t ah0[4], ah1[4];
            const uint32_t abase = sb + (uint32_t)(kq * 16 + (lane >> 4) * 8) * 2;
            LDMX4(ah0, abase + (uint32_t)(wrow + (lane & 15)) * 144);
            LDMX4(ah1, abase + (uint32_t)(wrow + 16 + (lane & 15)) * 144);
#pragma unroll
            for (int n = 0; n < 8; n++) {
                const uint32_t baddr = kvb + (uint32_t)(n * 8 + (lane & 7)) * 144
                                     + (uint32_t)(kq * 16 + ((lane >> 3) & 1) * 8) * 2;
                uint32_t kb[2];
                LDMX2(kb, baddr);
                MMA_F16(accs[0][n], ah0, kb);
                MMA_F16(accs[1][n], ah1, kb);
            }
        }

        // ---- mask + online softmax per m-tile ----
#pragma unroll
        for (int mi = 0; mi < 2; mi++) {
            const int r0 = qbase + wrow + mi * 16 + (lane >> 2);
            const float* mrow0 = mask + ((size_t)b * Sq + r0) * Sq + kt * 64 + (lane & 3) * 2;
            const float* mrow1 = mrow0 + 8 * Sq;
#pragma unroll
            for (int n = 0; n < 8; n++) {
                const float2 m0 = *(const float2*)(mrow0 + n * 8);
                const float2 m1 = *(const float2*)(mrow1 + n * 8);
                accs[mi][n][0] = fmaf(m0.x, -1e9f, accs[mi][n][0]);
                accs[mi][n][1] = fmaf(m0.y, -1e9f, accs[mi][n][1]);
                accs[mi][n][2] = fmaf(m1.x, -1e9f, accs[mi][n][2]);
                accs[mi][n][3] = fmaf(m1.y, -1e9f, accs[mi][n][3]);
            }

            float mx0 = -1e30f, mx1 = -1e30f;
#pragma unroll
            for (int n = 0; n < 8; n++) {
                mx0 = fmaxf(mx0, fmaxf(accs[mi][n][0], accs[mi][n][1]));
                mx1 = fmaxf(mx1, fmaxf(accs[mi][n][2], accs[mi][n][3]));
            }
            mx0 = fmaxf(mx0, __shfl_xor_sync(0xffffffffu, mx0, 1));
            mx0 = fmaxf(mx0, __shfl_xor_sync(0xffffffffu, mx0, 2));
            mx1 = fmaxf(mx1, __shfl_xor_sync(0xffffffffu, mx1, 1));
            mx1 = fmaxf(mx1, __shfl_xor_sync(0xffffffffu, mx1, 2));

            const float mn0 = fmaxf(m_st[mi][0], mx0);
            const float mn1 = fmaxf(m_st[mi][1], mx1);
            const float al0 = __expf(m_st[mi][0] - mn0);
            const float al1 = __expf(m_st[mi][1] - mn1);
            m_st[mi][0] = mn0; m_st[mi][1] = mn1;

            float sum0 = 0.f, sum1 = 0.f;
#pragma unroll
            for (int n = 0; n < 8; n++) {
                accs[mi][n][0] = __expf(accs[mi][n][0] - mn0);
                accs[mi][n][1] = __expf(accs[mi][n][1] - mn0);
                accs[mi][n][2] = __expf(accs[mi][n][2] - mn1);
                accs[mi][n][3] = __expf(accs[mi][n][3] - mn1);
                sum0 += accs[mi][n][0] + accs[mi][n][1];
                sum1 += accs[mi][n][2] + accs[mi][n][3];
            }
            sum0 += __shfl_xor_sync(0xffffffffu, sum0, 1);
            sum0 += __shfl_xor_sync(0xffffffffu, sum0, 2);
            sum1 += __shfl_xor_sync(0xffffffffu, sum1, 1);
            sum1 += __shfl_xor_sync(0xffffffffu, sum1, 2);
            l_st[mi][0] = l_st[mi][0] * al0 + sum0;
            l_st[mi][1] = l_st[mi][1] * al1 + sum1;

#pragma unroll
            for (int n = 0; n < 8; n++) {
                ctx[mi][n][0] *= al0; ctx[mi][n][1] *= al0;
                ctx[mi][n][2] *= al1; ctx[mi][n][3] *= al1;
            }
        }

        // ---- PV: V fragments shared by both m-tiles; pf transient ----
        const uint32_t vbase = kvb + KVTILE;
#pragma unroll
        for (int kk2 = 0; kk2 < 4; kk2++) {
            uint32_t pf0[4], pf1[4];
#pragma unroll
            for (int mi = 0; mi < 2; mi++) {
                uint32_t* pf = mi ? pf1 : pf0;
                __half2 p0 = __floats2half2_rn(accs[mi][2 * kk2][0],     accs[mi][2 * kk2][1]);
                __half2 p1 = __floats2half2_rn(accs[mi][2 * kk2][2],     accs[mi][2 * kk2][3]);
                __half2 p2 = __floats2half2_rn(accs[mi][2 * kk2 + 1][0], accs[mi][2 * kk2 + 1][1]);
                __half2 p3 = __floats2half2_rn(accs[mi][2 * kk2 + 1][2], accs[mi][2 * kk2 + 1][3]);
                pf[0] = *(uint32_t*)&p0; pf[1] = *(uint32_t*)&p1;
                pf[2] = *(uint32_t*)&p2; pf[3] = *(uint32_t*)&p3;
            }
#pragma unroll
            for (int n = 0; n < 8; n++) {
                const uint32_t vaddr = vbase + (uint32_t)(kk2 * 16 + (lane & 15)) * 144
                                     + (uint32_t)n * 16;
                uint32_t vh[2];
                LDMX2T(vh, vaddr);
                MMA_F16(ctx[0][n], pf0, vh);
                MMA_F16(ctx[1][n], pf1, vh);
            }
        }
        __syncthreads();
    }

    // ---- epilogue: ctx / l -> fp16 into g_xh [B*S, HID] ----
    const int cb = h * HDq + (lane & 3) * 2;
#pragma unroll
    for (int mi = 0; mi < 2; mi++) {
        const int r0 = qbase + wrow + mi * 16 + (lane >> 2);
        const float inv0 = 1.0f / l_st[mi][0];
        const float inv1 = 1.0f / l_st[mi][1];
#pragma unroll
        for (int n = 0; n < 8; n++) {
            const int col = cb + n * 8;
            const size_t off0 = ((size_t)(b * Sq + r0)) * HIDq + col;
            const size_t off1 = ((size_t)(b * Sq + r0 + 8)) * HIDq + col;
            __half2 h0 = __floats2half2_rn(ctx[mi][n][0] * inv0, ctx[mi][n][1] * inv0);
            __half2 h1 = __floats2half2_rn(ctx[mi][n][2] * inv1, ctx[mi][n][3] * inv1);
            *(uint32_t*)(g_xh + off0) = *(uint32_t*)&h0;
            *(uint32_t*)(g_xh + off1) = *(uint32_t*)&h1;
        }
    }
}

// ---------------------------------------------------------------------------
extern "C" void kernel_launch(void* const* d_in, const int* in_sizes, int n_in,
                              void* d_out, int out_size)
{
    (void)in_sizes; (void)n_in; (void)out_size;
    const float* x   = (const float*)d_in[0];
    const float* msk = (const float*)d_in[1];
    const float* Wq  = (const float*)d_in[2];
    const float* bq  = (const float*)d_in[3];
    const float* Wk  = (const float*)d_in[4];
    const float* bk  = (const float*)d_in[5];
    const float* Wv  = (const float*)d_in[6];
    const float* bv  = (const float*)d_in[7];
    const float* Wp  = (const float*)d_in[8];
    const float* bp  = (const float*)d_in[9];
    float* out = (float*)d_out;

    cudaFuncSetAttribute(gemm_qkv_kernel, cudaFuncAttributeMaxDynamicSharedMemorySize, GSMEM);
    cudaFuncSetAttribute(gemm_out_kernel, cudaFuncAttributeMaxDynamicSharedMemorySize, GSMEM);
    cudaFuncSetAttribute(attn_mma_kernel, cudaFuncAttributeMaxDynamicSharedMemorySize, ASMEM);

    convert_x_kernel<<<(Mq * HIDq) / (256 * 8), 256>>>(x);
    convw_all_kernel<<<dim3(32, 32, 4), 256>>>(Wq, Wk, Wv, Wp);

    gemm_qkv_kernel<<<dim3(HIDq / 128, Mq / 128, 3), 256, GSMEM>>>(bq, bk, bv);

    attn_mma_kernel<<<dim3(Sq / 256, Bq * NHq), 256, ASMEM>>>(msk);

    gemm_out_kernel<<<dim3(HIDq / 128, Mq / 128), 256, GSMEM>>>(bp, out);
}

// round 14
// speedup vs baseline: 1.1772x; 1.1772x over previous
#include <cuda_runtime.h>
#include <cuda_fp16.h>
#include <cstdint>

#define Bq   8
#define Sq   1024
#define HIDq 1024
#define NHq  16
#define HDq  64
#define Mq   (Bq * Sq)   // 8192

// Scratch (device globals: allocation-free per harness rules)
__device__ __half g_xh[(size_t)Mq * HIDq];     // A operand fp16 [M,K] (x, later ctx)
__device__ __half g_wt4[(size_t)4 * HIDq * HIDq];  // W^T fp16 [4][N,K] (q,k,v,p)
__device__ __half g_qh[(size_t)Bq * NHq * Sq * HDq];  // [B,NH,S,HD] (pre-scaled)
__device__ __half g_kh[(size_t)Bq * NHq * Sq * HDq];
__device__ __half g_vh[(size_t)Bq * NHq * Sq * HDq];

// ===========================================================================
// PTX helpers (portable tensor ISA: ldmatrix + mma.sync, sm_80+)
// ===========================================================================
__device__ __forceinline__ uint32_t smem_to_u32(const void* p) {
    uint32_t a;
    asm("{ .reg .u64 t; cvta.to.shared.u64 t, %1; cvt.u32.u64 %0, t; }"
        : "=r"(a) : "l"(p));
    return a;
}

#define LDMX4(r, addr) \
    asm volatile("ldmatrix.sync.aligned.m8n8.x4.shared.b16 {%0,%1,%2,%3}, [%4];" \
        : "=r"((r)[0]), "=r"((r)[1]), "=r"((r)[2]), "=r"((r)[3]) : "r"(addr))

#define LDMX2(r, addr) \
    asm volatile("ldmatrix.sync.aligned.m8n8.x2.shared.b16 {%0,%1}, [%2];" \
        : "=r"((r)[0]), "=r"((r)[1]) : "r"(addr))

#define LDMX2T(r, addr) \
    asm volatile("ldmatrix.sync.aligned.m8n8.x2.trans.shared.b16 {%0,%1}, [%2];" \
        : "=r"((r)[0]), "=r"((r)[1]) : "r"(addr))

#define MMA_F16(d, a, b) \
    asm volatile("mma.sync.aligned.m16n8k16.row.col.f32.f16.f16.f32 " \
        "{%0,%1,%2,%3}, {%4,%5,%6,%7}, {%8,%9}, {%0,%1,%2,%3};" \
        : "+f"((d)[0]), "+f"((d)[1]), "+f"((d)[2]), "+f"((d)[3]) \
        : "r"((a)[0]), "r"((a)[1]), "r"((a)[2]), "r"((a)[3]), \
          "r"((b)[0]), "r"((b)[1]))

#define CP_ASYNC16(smem, gmem) \
    asm volatile("cp.async.cg.shared.global [%0], [%1], 16;" \
        :: "r"(smem), "l"(gmem) : "memory")
#define CP_COMMIT()  asm volatile("cp.async.commit_group;" ::: "memory")
#define CP_WAIT(n)   asm volatile("cp.async.wait_group %0;" :: "n"(n) : "memory")

// ===========================================================================
// Conversion: x fp32 -> fp16
// ===========================================================================
__global__ __launch_bounds__(256) void convert_x_kernel(const float* __restrict__ src)
{
    const size_t i = ((size_t)blockIdx.x * 256 + threadIdx.x) * 8;
    float4 v0 = *(const float4*)(src + i);
    float4 v1 = *(const float4*)(src + i + 4);
    __half2 h0 = __floats2half2_rn(v0.x, v0.y);
    __half2 h1 = __floats2half2_rn(v0.z, v0.w);
    __half2 h2 = __floats2half2_rn(v1.x, v1.y);
    __half2 h3 = __floats2half2_rn(v1.z, v1.w);
    *(uint4*)(g_xh + i) = make_uint4(*(uint32_t*)&h0, *(uint32_t*)&h1,
                                     *(uint32_t*)&h2, *(uint32_t*)&h3);
}

// ===========================================================================
// All-weights transpose: g_wt4[z][n][k] = fp16(Wz[k][n]) for z in {q,k,v,p}
// ===========================================================================
__global__ __launch_bounds__(256) void convw_all_kernel(
    const float* __restrict__ W0, const float* __restrict__ W1,
    const float* __restrict__ W2, const float* __restrict__ W3)
{
    __shared__ float tile[32][33];
    const float* W = (blockIdx.z == 0) ? W0 : (blockIdx.z == 1) ? W1
                   : (blockIdx.z == 2) ? W2 : W3;
    __half* dst = g_wt4 + (size_t)blockIdx.z * HIDq * HIDq;
    const int bx = blockIdx.x * 32, by = blockIdx.y * 32;
    const int tx = threadIdx.x & 31, ty = threadIdx.x >> 5;  // 32 x 8
#pragma unroll
    for (int i = 0; i < 4; i++)
        tile[ty + i * 8][tx] = W[(size_t)(by + ty + i * 8) * HIDq + bx + tx];
    __syncthreads();
#pragma unroll
    for (int i = 0; i < 4; i++)
        dst[(size_t)(bx + ty + i * 8) * HIDq + by + tx] =
            __float2half(tile[tx][ty + i * 8]);
}

// ===========================================================================
// fp16 mma.sync GEMM core (R10 structure, 3-stage cp.async pipeline).
// KCH=64 (16 chunks). CTA 128x128, 8 warps (2m x 4n). Row stride 144 B.
// One __syncthreads per chunk (3-buffer rotation makes the tail sync safe
// to remove: issue(c+2) overwrites buf (c-1)%3, finished before this sync).
// ===========================================================================
#define KCH    64
#define GTILE  18432                    // 128 rows x 144 B
#define GSTG   (2 * GTILE)              // A + B per stage
#define GSMEM  (3 * GSTG)               // 110592 B, 3 stages
#define NCH    (HIDq / KCH)             // 16

// QKV merged GEMM: z = blockIdx.z selects weight slot, bias, destination.
__global__ __launch_bounds__(256, 2) void gemm_qkv_kernel(
    const float* __restrict__ b0, const float* __restrict__ b1,
    const float* __restrict__ b2)
{
    extern __shared__ char sm[];
    const uint32_t sb = smem_to_u32(sm);
    const int z = blockIdx.z;
    const __half* Wt = g_wt4 + (size_t)z * HIDq * HIDq;
    const float* bias = (z == 0) ? b0 : (z == 1) ? b1 : b2;
    __half* dst = (z == 0) ? g_qh : (z == 1) ? g_kh : g_vh;

    const int tid = threadIdx.x, lane = tid & 31, wid = tid >> 5;
    const int wm = wid >> 2, wn = wid & 3;
    const int bm = blockIdx.y * 128, bn = blockIdx.x * 128;

    float acc[4][4][4];
#pragma unroll
    for (int mi = 0; mi < 4; mi++)
#pragma unroll
        for (int ni = 0; ni < 4; ni++)
#pragma unroll
            for (int r = 0; r < 4; r++) acc[mi][ni][r] = 0.f;

    auto issue = [&](int c) {
        const uint32_t base = sb + (uint32_t)(c % 3) * GSTG;
        const int k0 = c * KCH;
#pragma unroll
        for (int t = 0; t < 4; t++) {
            const int id = t * 256 + tid;
            const int row = id >> 3, seg = id & 7;
            const uint32_t so = (uint32_t)row * 144 + seg * 16;
            CP_ASYNC16(base + so,         g_xh + (size_t)(bm + row) * HIDq + k0 + seg * 8);
            CP_ASYNC16(base + GTILE + so, Wt   + (size_t)(bn + row) * HIDq + k0 + seg * 8);
        }
        CP_COMMIT();
    };

    issue(0);
    issue(1);

    for (int c = 0; c < NCH; c++) {
        CP_WAIT(1);
        __syncthreads();

        const uint32_t base = sb + (uint32_t)(c % 3) * GSTG;

#pragma unroll
        for (int kk = 0; kk < KCH; kk += 16) {
            uint32_t bh[4][2];
#pragma unroll
            for (int ni = 0; ni < 4; ni++) {
                const uint32_t baddr = base + GTILE
                    + (uint32_t)(wn * 32 + ni * 8 + (lane & 7)) * 144
                    + (uint32_t)(kk + ((lane >> 3) & 1) * 8) * 2;
                LDMX2(bh[ni], baddr);
            }
#pragma unroll
            for (int mi = 0; mi < 4; mi++) {
                const uint32_t aaddr = base
                    + (uint32_t)(wm * 64 + mi * 16 + (lane & 15)) * 144
                    + (uint32_t)(kk + (lane >> 4) * 8) * 2;
                uint32_t ah[4];
                LDMX4(ah, aaddr);
#pragma unroll
                for (int ni = 0; ni < 4; ni++)
                    MMA_F16(acc[mi][ni], ah, bh[ni]);
            }
        }
        if (c + 2 < NCH) issue(c + 2);
    }

    const int rbase = bm + wm * 64 + (lane >> 2);
    const int cbase = bn + wn * 32 + (lane & 3) * 2;
    const float qs = (z == 0) ? 0.03125f : 1.0f;
#pragma unroll
    for (int mi = 0; mi < 4; mi++) {
#pragma unroll
        for (int ni = 0; ni < 4; ni++) {
            const int col = cbase + ni * 8;
            const float2 b2v = *(const float2*)(bias + col);
#pragma unroll
            for (int half = 0; half < 2; half++) {
                const int row = rbase + mi * 16 + half * 8;
                const float ox = (acc[mi][ni][half * 2 + 0] + b2v.x) * qs;
                const float oy = (acc[mi][ni][half * 2 + 1] + b2v.y) * qs;
                const int b = row >> 10, s = row & 1023;
                const int h = col >> 6,  d = col & 63;
                const size_t off = (((size_t)(b * NHq + h)) * Sq + s) * HDq + d;
                __half2 h2 = __floats2half2_rn(ox, oy);
                *(uint32_t*)(dst + off) = *(uint32_t*)&h2;
            }
        }
    }
}

// Output projection: A = g_xh (ctx), W slot 3, fp32 row-major to d_out.
__global__ __launch_bounds__(256, 2) void gemm_out_kernel(
    const float* __restrict__ bias, float* __restrict__ Cout)
{
    extern __shared__ char sm[];
    const uint32_t sb = smem_to_u32(sm);
    const __half* Wt = g_wt4 + (size_t)3 * HIDq * HIDq;

    const int tid = threadIdx.x, lane = tid & 31, wid = tid >> 5;
    const int wm = wid >> 2, wn = wid & 3;
    const int bm = blockIdx.y * 128, bn = blockIdx.x * 128;

    float acc[4][4][4];
#pragma unroll
    for (int mi = 0; mi < 4; mi++)
#pragma unroll
        for (int ni = 0; ni < 4; ni++)
#pragma unroll
            for (int r = 0; r < 4; r++) acc[mi][ni][r] = 0.f;

    auto issue = [&](int c) {
        const uint32_t base = sb + (uint32_t)(c % 3) * GSTG;
        const int k0 = c * KCH;
#pragma unroll
        for (int t = 0; t < 4; t++) {
            const int id = t * 256 + tid;
            const int row = id >> 3, seg = id & 7;
            const uint32_t so = (uint32_t)row * 144 + seg * 16;
            CP_ASYNC16(base + so,         g_xh + (size_t)(bm + row) * HIDq + k0 + seg * 8);
            CP_ASYNC16(base + GTILE + so, Wt   + (size_t)(bn + row) * HIDq + k0 + seg * 8);
        }
        CP_COMMIT();
    };

    issue(0);
    issue(1);

    for (int c = 0; c < NCH; c++) {
        CP_WAIT(1);
        __syncthreads();

        const uint32_t base = sb + (uint32_t)(c % 3) * GSTG;

#pragma unroll
        for (int kk = 0; kk < KCH; kk += 16) {
            uint32_t bh[4][2];
#pragma unroll
            for (int ni = 0; ni < 4; ni++) {
                const uint32_t baddr = base + GTILE
                    + (uint32_t)(wn * 32 + ni * 8 + (lane & 7)) * 144
                    + (uint32_t)(kk + ((lane >> 3) & 1) * 8) * 2;
                LDMX2(bh[ni], baddr);
            }
#pragma unroll
            for (int mi = 0; mi < 4; mi++) {
                const uint32_t aaddr = base
                    + (uint32_t)(wm * 64 + mi * 16 + (lane & 15)) * 144
                    + (uint32_t)(kk + (lane >> 4) * 8) * 2;
                uint32_t ah[4];
                LDMX4(ah, aaddr);
#pragma unroll
                for (int ni = 0; ni < 4; ni++)
                    MMA_F16(acc[mi][ni], ah, bh[ni]);
            }
        }
        if (c + 2 < NCH) issue(c + 2);
    }

    const int rbase = bm + wm * 64 + (lane >> 2);
    const int cbase = bn + wn * 32 + (lane & 3) * 2;
#pragma unroll
    for (int mi = 0; mi < 4; mi++) {
#pragma unroll
        for (int ni = 0; ni < 4; ni++) {
            const int col = cbase + ni * 8;
            const float2 b2v = *(const float2*)(bias + col);
#pragma unroll
            for (int half = 0; half < 2; half++) {
                const int row = rbase + mi * 16 + half * 8;
                *(float2*)(Cout + (size_t)row * HIDq + col) =
                    make_float2(acc[mi][ni][half * 2 + 0] + b2v.x,
                                acc[mi][ni][half * 2 + 1] + b2v.y);
            }
        }
    }
}

// ===========================================================================
// fp16 flash attention (R10 structure, 3-stage KV pipeline): 256 threads =
// 8 warps, warp owns 16 query rows; 128-query tile, 64-key stages.
// One __syncthreads per kt. smem 73.7 KB, 2 CTAs/SM.
// ctx -> fp16 into g_xh [B*S, HID].
// ===========================================================================
#define QTILE  18432                    // 128 rows x 144 B
#define KVTILE 9216                     // 64 rows x 144 B
#define KVSTG  (2 * KVTILE)             // Kh, Vh
#define KVOFF  QTILE
#define ASMEM  (KVOFF + 3 * KVSTG)      // 73728
#define NTK    (Sq / 64)                // 16

__global__ __launch_bounds__(256, 2) void attn_mma_kernel(const float* __restrict__ mask)
{
    extern __shared__ char sm[];
    const uint32_t sb = smem_to_u32(sm);

    const int bh = blockIdx.y;
    const int b = bh >> 4, h = bh & 15;
    const int qbase = blockIdx.x * 128;
    const int tid = threadIdx.x, lane = tid & 31, wid = tid >> 5;
    const int wrow = wid * 16;

    const size_t hb = (size_t)bh * Sq * HDq;
    const __half* Qg = g_qh + hb;
    const __half* KVg[2] = {g_kh + hb, g_vh + hb};

    // Q load (joins cp.async group 0 with KV stage 0)
#pragma unroll
    for (int t = 0; t < 4; t++) {
        const int id = t * 256 + tid;
        const int row = id >> 3, seg = id & 7;
        CP_ASYNC16(sb + (uint32_t)row * 144 + seg * 16,
                   Qg + (size_t)(qbase + row) * HDq + seg * 8);
    }

    auto issue_kv = [&](int kt) {
        const uint32_t base = sb + KVOFF + (uint32_t)(kt % 3) * KVSTG;
#pragma unroll
        for (int t = 0; t < 4; t++) {
            const int which = t >> 1;           // 0=Kh, 1=Vh
            const int id = (t & 1) * 256 + tid;
            const int row = id >> 3, seg = id & 7;
            CP_ASYNC16(base + (uint32_t)which * KVTILE + (uint32_t)row * 144 + seg * 16,
                       KVg[which] + (size_t)(kt * 64 + row) * HDq + seg * 8);
        }
        CP_COMMIT();
    };

    issue_kv(0);
    issue_kv(1);

    float m_st[2] = {-1e30f, -1e30f};
    float l_st[2] = {0.f, 0.f};
    float ctx[8][4];
#pragma unroll
    for (int n = 0; n < 8; n++)
#pragma unroll
        for (int r = 0; r < 4; r++) ctx[n][r] = 0.f;

    const int r0 = qbase + wrow + (lane >> 2);

    for (int kt = 0; kt < NTK; kt++) {
        CP_WAIT(1);
        __syncthreads();

        const uint32_t kvb = sb + KVOFF + (uint32_t)(kt % 3) * KVSTG;

        // ---- scores S = Q K^T ----
        float accs[8][4];
#pragma unroll
        for (int n = 0; n < 8; n++)
#pragma unroll
            for (int r = 0; r < 4; r++) accs[n][r] = 0.f;

#pragma unroll
        for (int k0 = 0; k0 < 64; k0 += 16) {
            uint32_t ah[4];
            const uint32_t aaddr = sb + (uint32_t)(wrow + (lane & 15)) * 144
                                 + (uint32_t)(k0 + (lane >> 4) * 8) * 2;
            LDMX4(ah, aaddr);
#pragma unroll
            for (int n = 0; n < 8; n++) {
                const uint32_t baddr = kvb + (uint32_t)(n * 8 + (lane & 7)) * 144
                                     + (uint32_t)(k0 + ((lane >> 3) & 1) * 8) * 2;
                uint32_t kb[2];
                LDMX2(kb, baddr);
                MMA_F16(accs[n], ah, kb);
            }
        }

        // ---- mask (scale already folded into Q) ----
        const float* mrow0 = mask + ((size_t)b * Sq + r0) * Sq + kt * 64 + (lane & 3) * 2;
        const float* mrow1 = mrow0 + 8 * Sq;
#pragma unroll
        for (int n = 0; n < 8; n++) {
            const float2 m0 = *(const float2*)(mrow0 + n * 8);
            const float2 m1 = *(const float2*)(mrow1 + n * 8);
            accs[n][0] = fmaf(m0.x, -1e9f, accs[n][0]);
            accs[n][1] = fmaf(m0.y, -1e9f, accs[n][1]);
            accs[n][2] = fmaf(m1.x, -1e9f, accs[n][2]);
            accs[n][3] = fmaf(m1.y, -1e9f, accs[n][3]);
        }

        // ---- online softmax (rows r0, r0+8) ----
        float mx0 = -1e30f, mx1 = -1e30f;
#pragma unroll
        for (int n = 0; n < 8; n++) {
            mx0 = fmaxf(mx0, fmaxf(accs[n][0], accs[n][1]));
            mx1 = fmaxf(mx1, fmaxf(accs[n][2], accs[n][3]));
        }
        mx0 = fmaxf(mx0, __shfl_xor_sync(0xffffffffu, mx0, 1));
        mx0 = fmaxf(mx0, __shfl_xor_sync(0xffffffffu, mx0, 2));
        mx1 = fmaxf(mx1, __shfl_xor_sync(0xffffffffu, mx1, 1));
        mx1 = fmaxf(mx1, __shfl_xor_sync(0xffffffffu, mx1, 2));

        const float mn0 = fmaxf(m_st[0], mx0);
        const float mn1 = fmaxf(m_st[1], mx1);
        const float al0 = __expf(m_st[0] - mn0);
        const float al1 = __expf(m_st[1] - mn1);
        m_st[0] = mn0; m_st[1] = mn1;

        float sum0 = 0.f, sum1 = 0.f;
#pragma unroll
        for (int n = 0; n < 8; n++) {
            accs[n][0] = __expf(accs[n][0] - mn0);
            accs[n][1] = __expf(accs[n][1] - mn0);
            accs[n][2] = __expf(accs[n][2] - mn1);
            accs[n][3] = __expf(accs[n][3] - mn1);
            sum0 += accs[n][0] + accs[n][1];
            sum1 += accs[n][2] + accs[n][3];
        }
        sum0 += __shfl_xor_sync(0xffffffffu, sum0, 1);
        sum0 += __shfl_xor_sync(0xffffffffu, sum0, 2);
        sum1 += __shfl_xor_sync(0xffffffffu, sum1, 1);
        sum1 += __shfl_xor_sync(0xffffffffu, sum1, 2);
        l_st[0] = l_st[0] * al0 + sum0;
        l_st[1] = l_st[1] * al1 + sum1;

#pragma unroll
        for (int n = 0; n < 8; n++) {
            ctx[n][0] *= al0; ctx[n][1] *= al0;
            ctx[n][2] *= al1; ctx[n][3] *= al1;
        }

        // ---- PV: ctx += P_fp16 V ----
        const uint32_t vbase = kvb + KVTILE;
#pragma unroll
        for (int kk2 = 0; kk2 < 4; kk2++) {
            uint32_t pf[4];
            __half2 p0 = __floats2half2_rn(accs[2 * kk2][0],     accs[2 * kk2][1]);
            __half2 p1 = __floats2half2_rn(accs[2 * kk2][2],     accs[2 * kk2][3]);
            __half2 p2 = __floats2half2_rn(accs[2 * kk2 + 1][0], accs[2 * kk2 + 1][1]);
            __half2 p3 = __floats2half2_rn(accs[2 * kk2 + 1][2], accs[2 * kk2 + 1][3]);
            pf[0] = *(uint32_t*)&p0; pf[1] = *(uint32_t*)&p1;
            pf[2] = *(uint32_t*)&p2; pf[3] = *(uint32_t*)&p3;
#pragma unroll
            for (int n = 0; n < 8; n++) {
                const uint32_t vaddr = vbase + (uint32_t)(kk2 * 16 + (lane & 15)) * 144
                                     + (uint32_t)n * 16;
                uint32_t vh[2];
                LDMX2T(vh, vaddr);
                MMA_F16(ctx[n], pf, vh);
            }
        }

        if (kt + 2 < NTK) issue_kv(kt + 2);
    }

    // ---- epilogue: ctx / l -> fp16 into g_xh [B*S, HID] ----
    const float inv0 = 1.0f / l_st[0];
    const float inv1 = 1.0f / l_st[1];
    const int cb = h * HDq + (lane & 3) * 2;
#pragma unroll
    for (int n = 0; n < 8; n++) {
        const int col = cb + n * 8;
        const size_t off0 = ((size_t)(b * Sq + r0)) * HIDq + col;
        const size_t off1 = ((size_t)(b * Sq + r0 + 8)) * HIDq + col;
        __half2 h0 = __floats2half2_rn(ctx[n][0] * inv0, ctx[n][1] * inv0);
        __half2 h1 = __floats2half2_rn(ctx[n][2] * inv1, ctx[n][3] * inv1);
        *(uint32_t*)(g_xh + off0) = *(uint32_t*)&h0;
        *(uint32_t*)(g_xh + off1) = *(uint32_t*)&h1;
    }
}

// ---------------------------------------------------------------------------
extern "C" void kernel_launch(void* const* d_in, const int* in_sizes, int n_in,
                              void* d_out, int out_size)
{
    (void)in_sizes; (void)n_in; (void)out_size;
    const float* x   = (const float*)d_in[0];
    const float* msk = (const float*)d_in[1];
    const float* Wq  = (const float*)d_in[2];
    const float* bq  = (const float*)d_in[3];
    const float* Wk  = (const float*)d_in[4];
    const float* bk  = (const float*)d_in[5];
    const float* Wv  = (const float*)d_in[6];
    const float* bv  = (const float*)d_in[7];
    const float* Wp  = (const float*)d_in[8];
    const float* bp  = (const float*)d_in[9];
    float* out = (float*)d_out;

    cudaFuncSetAttribute(gemm_qkv_kernel, cudaFuncAttributeMaxDynamicSharedMemorySize, GSMEM);
    cudaFuncSetAttribute(gemm_out_kernel, cudaFuncAttributeMaxDynamicSharedMemorySize, GSMEM);
    cudaFuncSetAttribute(attn_mma_kernel, cudaFuncAttributeMaxDynamicSharedMemorySize, ASMEM);

    convert_x_kernel<<<(Mq * HIDq) / (256 * 8), 256>>>(x);
    convw_all_kernel<<<dim3(32, 32, 4), 256>>>(Wq, Wk, Wv, Wp);

    gemm_qkv_kernel<<<dim3(HIDq / 128, Mq / 128, 3), 256, GSMEM>>>(bq, bk, bv);

    attn_mma_kernel<<<dim3(Sq / 128, Bq * NHq), 256, ASMEM>>>(msk);

    gemm_out_kernel<<<dim3(HIDq / 128, Mq / 128), 256, GSMEM>>>(bp, out);
}

// round 15
// speedup vs baseline: 1.1916x; 1.0123x over previous
#include <cuda_runtime.h>
#include <cuda_fp16.h>
#include <cstdint>

#define Bq   8
#define Sq   1024
#define HIDq 1024
#define NHq  16
#define HDq  64
#define Mq   (Bq * Sq)   // 8192

// Scratch (device globals: allocation-free per harness rules)
__device__ __half g_xh[(size_t)Mq * HIDq];     // A operand fp16 [M,K] (x, later ctx)
__device__ __half g_wt4[(size_t)4 * HIDq * HIDq];  // W^T fp16 [4][N,K] (q,k,v,p)
__device__ __half g_qh[(size_t)Bq * NHq * Sq * HDq];  // [B,NH,S,HD] (pre-scaled by rsqrt(HID)*log2e)
__device__ __half g_kh[(size_t)Bq * NHq * Sq * HDq];
__device__ __half g_vh[(size_t)Bq * NHq * Sq * HDq];

// ===========================================================================
// PTX helpers (portable tensor ISA: ldmatrix + mma.sync, sm_80+)
// ===========================================================================
__device__ __forceinline__ uint32_t smem_to_u32(const void* p) {
    uint32_t a;
    asm("{ .reg .u64 t; cvta.to.shared.u64 t, %1; cvt.u32.u64 %0, t; }"
        : "=r"(a) : "l"(p));
    return a;
}

#define LDMX4(r, addr) \
    asm volatile("ldmatrix.sync.aligned.m8n8.x4.shared.b16 {%0,%1,%2,%3}, [%4];" \
        : "=r"((r)[0]), "=r"((r)[1]), "=r"((r)[2]), "=r"((r)[3]) : "r"(addr))

#define LDMX2(r, addr) \
    asm volatile("ldmatrix.sync.aligned.m8n8.x2.shared.b16 {%0,%1}, [%2];" \
        : "=r"((r)[0]), "=r"((r)[1]) : "r"(addr))

#define LDMX2T(r, addr) \
    asm volatile("ldmatrix.sync.aligned.m8n8.x2.trans.shared.b16 {%0,%1}, [%2];" \
        : "=r"((r)[0]), "=r"((r)[1]) : "r"(addr))

#define MMA_F16(d, a, b) \
    asm volatile("mma.sync.aligned.m16n8k16.row.col.f32.f16.f16.f32 " \
        "{%0,%1,%2,%3}, {%4,%5,%6,%7}, {%8,%9}, {%0,%1,%2,%3};" \
        : "+f"((d)[0]), "+f"((d)[1]), "+f"((d)[2]), "+f"((d)[3]) \
        : "r"((a)[0]), "r"((a)[1]), "r"((a)[2]), "r"((a)[3]), \
          "r"((b)[0]), "r"((b)[1]))

#define CP_ASYNC16(smem, gmem) \
    asm volatile("cp.async.cg.shared.global [%0], [%1], 16;" \
        :: "r"(smem), "l"(gmem) : "memory")
#define CP_COMMIT()  asm volatile("cp.async.commit_group;" ::: "memory")
#define CP_WAIT(n)   asm volatile("cp.async.wait_group %0;" :: "n"(n) : "memory")

#define LOG2E 1.44269504f

// ===========================================================================
// Conversion: x fp32 -> fp16
// ===========================================================================
__global__ __launch_bounds__(256) void convert_x_kernel(const float* __restrict__ src)
{
    const size_t i = ((size_t)blockIdx.x * 256 + threadIdx.x) * 8;
    float4 v0 = *(const float4*)(src + i);
    float4 v1 = *(const float4*)(src + i + 4);
    __half2 h0 = __floats2half2_rn(v0.x, v0.y);
    __half2 h1 = __floats2half2_rn(v0.z, v0.w);
    __half2 h2 = __floats2half2_rn(v1.x, v1.y);
    __half2 h3 = __floats2half2_rn(v1.z, v1.w);
    *(uint4*)(g_xh + i) = make_uint4(*(uint32_t*)&h0, *(uint32_t*)&h1,
                                     *(uint32_t*)&h2, *(uint32_t*)&h3);
}

// ===========================================================================
// All-weights transpose: g_wt4[z][n][k] = fp16(Wz[k][n]) for z in {q,k,v,p}
// ===========================================================================
__global__ __launch_bounds__(256) void convw_all_kernel(
    const float* __restrict__ W0, const float* __restrict__ W1,
    const float* __restrict__ W2, const float* __restrict__ W3)
{
    __shared__ float tile[32][33];
    const float* W = (blockIdx.z == 0) ? W0 : (blockIdx.z == 1) ? W1
                   : (blockIdx.z == 2) ? W2 : W3;
    __half* dst = g_wt4 + (size_t)blockIdx.z * HIDq * HIDq;
    const int bx = blockIdx.x * 32, by = blockIdx.y * 32;
    const int tx = threadIdx.x & 31, ty = threadIdx.x >> 5;  // 32 x 8
#pragma unroll
    for (int i = 0; i < 4; i++)
        tile[ty + i * 8][tx] = W[(size_t)(by + ty + i * 8) * HIDq + bx + tx];
    __syncthreads();
#pragma unroll
    for (int i = 0; i < 4; i++)
        dst[(size_t)(bx + ty + i * 8) * HIDq + by + tx] =
            __float2half(tile[tx][ty + i * 8]);
}

// ===========================================================================
// fp16 mma.sync GEMM core (3-stage cp.async pipeline, R14-proven).
// KCH=64 (16 chunks). CTA 128x128, 8 warps (2m x 4n). Row stride 144 B.
// ===========================================================================
#define KCH    64
#define GTILE  18432                    // 128 rows x 144 B
#define GSTG   (2 * GTILE)              // A + B per stage
#define GSMEM  (3 * GSTG)               // 110592 B, 3 stages
#define NCH    (HIDq / KCH)             // 16

// QKV merged GEMM: z = blockIdx.z selects weight slot, bias, destination.
__global__ __launch_bounds__(256, 2) void gemm_qkv_kernel(
    const float* __restrict__ b0, const float* __restrict__ b1,
    const float* __restrict__ b2)
{
    extern __shared__ char sm[];
    const uint32_t sb = smem_to_u32(sm);
    const int z = blockIdx.z;
    const __half* Wt = g_wt4 + (size_t)z * HIDq * HIDq;
    const float* bias = (z == 0) ? b0 : (z == 1) ? b1 : b2;
    __half* dst = (z == 0) ? g_qh : (z == 1) ? g_kh : g_vh;

    const int tid = threadIdx.x, lane = tid & 31, wid = tid >> 5;
    const int wm = wid >> 2, wn = wid & 3;
    const int bm = blockIdx.y * 128, bn = blockIdx.x * 128;

    float acc[4][4][4];
#pragma unroll
    for (int mi = 0; mi < 4; mi++)
#pragma unroll
        for (int ni = 0; ni < 4; ni++)
#pragma unroll
            for (int r = 0; r < 4; r++) acc[mi][ni][r] = 0.f;

    auto issue = [&](int c) {
        const uint32_t base = sb + (uint32_t)(c % 3) * GSTG;
        const int k0 = c * KCH;
#pragma unroll
        for (int t = 0; t < 4; t++) {
            const int id = t * 256 + tid;
            const int row = id >> 3, seg = id & 7;
            const uint32_t so = (uint32_t)row * 144 + seg * 16;
            CP_ASYNC16(base + so,         g_xh + (size_t)(bm + row) * HIDq + k0 + seg * 8);
            CP_ASYNC16(base + GTILE + so, Wt   + (size_t)(bn + row) * HIDq + k0 + seg * 8);
        }
        CP_COMMIT();
    };

    issue(0);
    issue(1);

    for (int c = 0; c < NCH; c++) {
        CP_WAIT(1);
        __syncthreads();

        const uint32_t base = sb + (uint32_t)(c % 3) * GSTG;

#pragma unroll
        for (int kk = 0; kk < KCH; kk += 16) {
            uint32_t bh[4][2];
#pragma unroll
            for (int ni = 0; ni < 4; ni++) {
                const uint32_t baddr = base + GTILE
                    + (uint32_t)(wn * 32 + ni * 8 + (lane & 7)) * 144
                    + (uint32_t)(kk + ((lane >> 3) & 1) * 8) * 2;
                LDMX2(bh[ni], baddr);
            }
#pragma unroll
            for (int mi = 0; mi < 4; mi++) {
                const uint32_t aaddr = base
                    + (uint32_t)(wm * 64 + mi * 16 + (lane & 15)) * 144
                    + (uint32_t)(kk + (lane >> 4) * 8) * 2;
                uint32_t ah[4];
                LDMX4(ah, aaddr);
#pragma unroll
                for (int ni = 0; ni < 4; ni++)
                    MMA_F16(acc[mi][ni], ah, bh[ni]);
            }
        }
        if (c + 2 < NCH) issue(c + 2);
    }

    const int rbase = bm + wm * 64 + (lane >> 2);
    const int cbase = bn + wn * 32 + (lane & 3) * 2;
    // Q pre-scale includes log2(e) so attention scores live in log2 domain.
    const float qs = (z == 0) ? 0.03125f * LOG2E : 1.0f;
#pragma unroll
    for (int mi = 0; mi < 4; mi++) {
#pragma unroll
        for (int ni = 0; ni < 4; ni++) {
            const int col = cbase + ni * 8;
            const float2 b2v = *(const float2*)(bias + col);
#pragma unroll
            for (int half = 0; half < 2; half++) {
                const int row = rbase + mi * 16 + half * 8;
                const float ox = (acc[mi][ni][half * 2 + 0] + b2v.x) * qs;
                const float oy = (acc[mi][ni][half * 2 + 1] + b2v.y) * qs;
                const int b = row >> 10, s = row & 1023;
                const int h = col >> 6,  d = col & 63;
                const size_t off = (((size_t)(b * NHq + h)) * Sq + s) * HDq + d;
                __half2 h2 = __floats2half2_rn(ox, oy);
                *(uint32_t*)(dst + off) = *(uint32_t*)&h2;
            }
        }
    }
}

// Output projection: A = g_xh (ctx), W slot 3, fp32 row-major to d_out.
__global__ __launch_bounds__(256, 2) void gemm_out_kernel(
    const float* __restrict__ bias, float* __restrict__ Cout)
{
    extern __shared__ char sm[];
    const uint32_t sb = smem_to_u32(sm);
    const __half* Wt = g_wt4 + (size_t)3 * HIDq * HIDq;

    const int tid = threadIdx.x, lane = tid & 31, wid = tid >> 5;
    const int wm = wid >> 2, wn = wid & 3;
    const int bm = blockIdx.y * 128, bn = blockIdx.x * 128;

    float acc[4][4][4];
#pragma unroll
    for (int mi = 0; mi < 4; mi++)
#pragma unroll
        for (int ni = 0; ni < 4; ni++)
#pragma unroll
            for (int r = 0; r < 4; r++) acc[mi][ni][r] = 0.f;

    auto issue = [&](int c) {
        const uint32_t base = sb + (uint32_t)(c % 3) * GSTG;
        const int k0 = c * KCH;
#pragma unroll
        for (int t = 0; t < 4; t++) {
            const int id = t * 256 + tid;
            const int row = id >> 3, seg = id & 7;
            const uint32_t so = (uint32_t)row * 144 + seg * 16;
            CP_ASYNC16(base + so,         g_xh + (size_t)(bm + row) * HIDq + k0 + seg * 8);
            CP_ASYNC16(base + GTILE + so, Wt   + (size_t)(bn + row) * HIDq + k0 + seg * 8);
        }
        CP_COMMIT();
    };

    issue(0);
    issue(1);

    for (int c = 0; c < NCH; c++) {
        CP_WAIT(1);
        __syncthreads();

        const uint32_t base = sb + (uint32_t)(c % 3) * GSTG;

#pragma unroll
        for (int kk = 0; kk < KCH; kk += 16) {
            uint32_t bh[4][2];
#pragma unroll
            for (int ni = 0; ni < 4; ni++) {
                const uint32_t baddr = base + GTILE
                    + (uint32_t)(wn * 32 + ni * 8 + (lane & 7)) * 144
                    + (uint32_t)(kk + ((lane >> 3) & 1) * 8) * 2;
                LDMX2(bh[ni], baddr);
            }
#pragma unroll
            for (int mi = 0; mi < 4; mi++) {
                const uint32_t aaddr = base
                    + (uint32_t)(wm * 64 + mi * 16 + (lane & 15)) * 144
                    + (uint32_t)(kk + (lane >> 4) * 8) * 2;
                uint32_t ah[4];
                LDMX4(ah, aaddr);
#pragma unroll
                for (int ni = 0; ni < 4; ni++)
                    MMA_F16(acc[mi][ni], ah, bh[ni]);
            }
        }
        if (c + 2 < NCH) issue(c + 2);
    }

    const int rbase = bm + wm * 64 + (lane >> 2);
    const int cbase = bn + wn * 32 + (lane & 3) * 2;
#pragma unroll
    for (int mi = 0; mi < 4; mi++) {
#pragma unroll
        for (int ni = 0; ni < 4; ni++) {
            const int col = cbase + ni * 8;
            const float2 b2v = *(const float2*)(bias + col);
#pragma unroll
            for (int half = 0; half < 2; half++) {
                const int row = rbase + mi * 16 + half * 8;
                *(float2*)(Cout + (size_t)row * HIDq + col) =
                    make_float2(acc[mi][ni][half * 2 + 0] + b2v.x,
                                acc[mi][ni][half * 2 + 1] + b2v.y);
            }
        }
    }
}

// ===========================================================================
// fp16 flash attention (R14 structure + log2-domain softmax with h2exp2):
// 256 threads = 8 warps, warp owns 16 query rows; 128-query tile, 64-key
// stages, 3-stage KV pipeline, one __syncthreads per kt. smem 73.7 KB.
// Scores arrive pre-scaled by rsqrt(HID)*log2e; mask coeff -1e9*log2e;
// p = exp2(s - m) computed as fp16x2 MUFU (2 exps/op), feeding PV directly.
// ctx -> fp16 into g_xh [B*S, HID].
// ===========================================================================
#define QTILE  18432                    // 128 rows x 144 B
#define KVTILE 9216                     // 64 rows x 144 B
#define KVSTG  (2 * KVTILE)             // Kh, Vh
#define KVOFF  QTILE
#define ASMEM  (KVOFF + 3 * KVSTG)      // 73728
#define NTK    (Sq / 64)                // 16

__global__ __launch_bounds__(256, 2) void attn_mma_kernel(const float* __restrict__ mask)
{
    extern __shared__ char sm[];
    const uint32_t sb = smem_to_u32(sm);

    const int bh = blockIdx.y;
    const int b = bh >> 4, h = bh & 15;
    const int qbase = blockIdx.x * 128;
    const int tid = threadIdx.x, lane = tid & 31, wid = tid >> 5;
    const int wrow = wid * 16;

    const size_t hb = (size_t)bh * Sq * HDq;
    const __half* Qg = g_qh + hb;
    const __half* KVg[2] = {g_kh + hb, g_vh + hb};

    // Q load (joins cp.async group 0 with KV stage 0)
#pragma unroll
    for (int t = 0; t < 4; t++) {
        const int id = t * 256 + tid;
        const int row = id >> 3, seg = id & 7;
        CP_ASYNC16(sb + (uint32_t)row * 144 + seg * 16,
                   Qg + (size_t)(qbase + row) * HDq + seg * 8);
    }

    auto issue_kv = [&](int kt) {
        const uint32_t base = sb + KVOFF + (uint32_t)(kt % 3) * KVSTG;
#pragma unroll
        for (int t = 0; t < 4; t++) {
            const int which = t >> 1;           // 0=Kh, 1=Vh
            const int id = (t & 1) * 256 + tid;
            const int row = id >> 3, seg = id & 7;
            CP_ASYNC16(base + (uint32_t)which * KVTILE + (uint32_t)row * 144 + seg * 16,
                       KVg[which] + (size_t)(kt * 64 + row) * HDq + seg * 8);
        }
        CP_COMMIT();
    };

    issue_kv(0);
    issue_kv(1);

    float m_st[2] = {-1e30f, -1e30f};
    float l_st[2] = {0.f, 0.f};
    float ctx[8][4];
#pragma unroll
    for (int n = 0; n < 8; n++)
#pragma unroll
        for (int r = 0; r < 4; r++) ctx[n][r] = 0.f;

    const int r0 = qbase + wrow + (lane >> 2);
    const float MSCALE = -1e9f * LOG2E;

    for (int kt = 0; kt < NTK; kt++) {
        CP_WAIT(1);
        __syncthreads();

        const uint32_t kvb = sb + KVOFF + (uint32_t)(kt % 3) * KVSTG;

        // ---- scores S = Q K^T (log2 domain: Q pre-scaled by scale*log2e) ----
        float accs[8][4];
#pragma unroll
        for (int n = 0; n < 8; n++)
#pragma unroll
            for (int r = 0; r < 4; r++) accs[n][r] = 0.f;

#pragma unroll
        for (int k0 = 0; k0 < 64; k0 += 16) {
            uint32_t ah[4];
            const uint32_t aaddr = sb + (uint32_t)(wrow + (lane & 15)) * 144
                                 + (uint32_t)(k0 + (lane >> 4) * 8) * 2;
            LDMX4(ah, aaddr);
#pragma unroll
            for (int n = 0; n < 8; n++) {
                const uint32_t baddr = kvb + (uint32_t)(n * 8 + (lane & 7)) * 144
                                     + (uint32_t)(k0 + ((lane >> 3) & 1) * 8) * 2;
                uint32_t kb[2];
                LDMX2(kb, baddr);
                MMA_F16(accs[n], ah, kb);
            }
        }

        // ---- mask (coeff folded with log2e) ----
        const float* mrow0 = mask + ((size_t)b * Sq + r0) * Sq + kt * 64 + (lane & 3) * 2;
        const float* mrow1 = mrow0 + 8 * Sq;
#pragma unroll
        for (int n = 0; n < 8; n++) {
            const float2 m0 = *(const float2*)(mrow0 + n * 8);
            const float2 m1 = *(const float2*)(mrow1 + n * 8);
            accs[n][0] = fmaf(m0.x, MSCALE, accs[n][0]);
            accs[n][1] = fmaf(m0.y, MSCALE, accs[n][1]);
            accs[n][2] = fmaf(m1.x, MSCALE, accs[n][2]);
            accs[n][3] = fmaf(m1.y, MSCALE, accs[n][3]);
        }

        // ---- online softmax stats (rows r0, r0+8), base-2 ----
        float mx0 = -1e30f, mx1 = -1e30f;
#pragma unroll
        for (int n = 0; n < 8; n++) {
            mx0 = fmaxf(mx0, fmaxf(accs[n][0], accs[n][1]));
            mx1 = fmaxf(mx1, fmaxf(accs[n][2], accs[n][3]));
        }
        mx0 = fmaxf(mx0, __shfl_xor_sync(0xffffffffu, mx0, 1));
        mx0 = fmaxf(mx0, __shfl_xor_sync(0xffffffffu, mx0, 2));
        mx1 = fmaxf(mx1, __shfl_xor_sync(0xffffffffu, mx1, 1));
        mx1 = fmaxf(mx1, __shfl_xor_sync(0xffffffffu, mx1, 2));

        const float mn0 = fmaxf(m_st[0], mx0);
        const float mn1 = fmaxf(m_st[1], mx1);
        const float al0 = exp2f(m_st[0] - mn0);
        const float al1 = exp2f(m_st[1] - mn1);
        m_st[0] = mn0; m_st[1] = mn1;

#pragma unroll
        for (int n = 0; n < 8; n++) {
            ctx[n][0] *= al0; ctx[n][1] *= al0;
            ctx[n][2] *= al1; ctx[n][3] *= al1;
        }

        // ---- PV with fused fp16x2 exp2: p = exp2(s - m) as half2, sums in half2 ----
        const uint32_t vbase = kvb + KVTILE;
        __half2 sh0 = __floats2half2_rn(0.f, 0.f);
        __half2 sh1 = sh0;
#pragma unroll
        for (int kk2 = 0; kk2 < 4; kk2++) {
            __half2 t0 = __floats2half2_rn(accs[2 * kk2][0] - mn0,     accs[2 * kk2][1] - mn0);
            __half2 t1 = __floats2half2_rn(accs[2 * kk2][2] - mn1,     accs[2 * kk2][3] - mn1);
            __half2 t2 = __floats2half2_rn(accs[2 * kk2 + 1][0] - mn0, accs[2 * kk2 + 1][1] - mn0);
            __half2 t3 = __floats2half2_rn(accs[2 * kk2 + 1][2] - mn1, accs[2 * kk2 + 1][3] - mn1);
            __half2 p0 = h2exp2(t0);
            __half2 p1 = h2exp2(t1);
            __half2 p2 = h2exp2(t2);
            __half2 p3 = h2exp2(t3);
            sh0 = __hadd2(sh0, __hadd2(p0, p2));
            sh1 = __hadd2(sh1, __hadd2(p1, p3));
            uint32_t pf[4];
            pf[0] = *(uint32_t*)&p0; pf[1] = *(uint32_t*)&p1;
            pf[2] = *(uint32_t*)&p2; pf[3] = *(uint32_t*)&p3;
#pragma unroll
            for (int n = 0; n < 8; n++) {
                const uint32_t vaddr = vbase + (uint32_t)(kk2 * 16 + (lane & 15)) * 144
                                     + (uint32_t)n * 16;
                uint32_t vh[2];
                LDMX2T(vh, vaddr);
                MMA_F16(ctx[n], pf, vh);
            }
        }

        // ---- l update (promote half2 sums to fp32, quad-reduce) ----
        float2 s0f = __half22float2(sh0);
        float2 s1f = __half22float2(sh1);
        float sum0 = s0f.x + s0f.y;
        float sum1 = s1f.x + s1f.y;
        sum0 += __shfl_xor_sync(0xffffffffu, sum0, 1);
        sum0 += __shfl_xor_sync(0xffffffffu, sum0, 2);
        sum1 += __shfl_xor_sync(0xffffffffu, sum1, 1);
        sum1 += __shfl_xor_sync(0xffffffffu, sum1, 2);
        l_st[0] = l_st[0] * al0 + sum0;
        l_st[1] = l_st[1] * al1 + sum1;

        if (kt + 2 < NTK) issue_kv(kt + 2);
    }

    // ---- epilogue: ctx / l -> fp16 into g_xh [B*S, HID] ----
    const float inv0 = 1.0f / l_st[0];
    const float inv1 = 1.0f / l_st[1];
    const int cb = h * HDq + (lane & 3) * 2;
#pragma unroll
    for (int n = 0; n < 8; n++) {
        const int col = cb + n * 8;
        const size_t off0 = ((size_t)(b * Sq + r0)) * HIDq + col;
        const size_t off1 = ((size_t)(b * Sq + r0 + 8)) * HIDq + col;
        __half2 h0 = __floats2half2_rn(ctx[n][0] * inv0, ctx[n][1] * inv0);
        __half2 h1 = __floats2half2_rn(ctx[n][2] * inv1, ctx[n][3] * inv1);
        *(uint32_t*)(g_xh + off0) = *(uint32_t*)&h0;
        *(uint32_t*)(g_xh + off1) = *(uint32_t*)&h1;
    }
}

// ---------------------------------------------------------------------------
extern "C" void kernel_launch(void* const* d_in, const int* in_sizes, int n_in,
                              void* d_out, int out_size)
{
    (void)in_sizes; (void)n_in; (void)out_size;
    const float* x   = (const float*)d_in[0];
    const float* msk = (const float*)d_in[1];
    const float* Wq  = (const float*)d_in[2];
    const float* bq  = (const float*)d_in[3];
    const float* Wk  = (const float*)d_in[4];
    const float* bk  = (const float*)d_in[5];
    const float* Wv  = (const float*)d_in[6];
    const float* bv  = (const float*)d_in[7];
    const float* Wp  = (const float*)d_in[8];
    const float* bp  = (const float*)d_in[9];
    float* out = (float*)d_out;

    cudaFuncSetAttribute(gemm_qkv_kernel, cudaFuncAttributeMaxDynamicSharedMemorySize, GSMEM);
    cudaFuncSetAttribute(gemm_out_kernel, cudaFuncAttributeMaxDynamicSharedMemorySize, GSMEM);
    cudaFuncSetAttribute(attn_mma_kernel, cudaFuncAttributeMaxDynamicSharedMemorySize, ASMEM);

    convert_x_kernel<<<(Mq * HIDq) / (256 * 8), 256>>>(x);
    convw_all_kernel<<<dim3(32, 32, 4), 256>>>(Wq, Wk, Wv, Wp);

    gemm_qkv_kernel<<<dim3(HIDq / 128, Mq / 128, 3), 256, GSMEM>>>(bq, bk, bv);

    attn_mma_kernel<<<dim3(Sq / 128, Bq * NHq), 256, ASMEM>>>(msk);

    gemm_out_kernel<<<dim3(HIDq / 128, Mq / 128), 256, GSMEM>>>(bp, out);
}

// round 16
// speedup vs baseline: 1.2244x; 1.0275x over previous
#include <cuda_runtime.h>
#include <cuda_fp16.h>
#include <cstdint>

#define Bq   8
#define Sq   1024
#define HIDq 1024
#define NHq  16
#define HDq  64
#define Mq   (Bq * Sq)   // 8192

// Scratch (device globals: allocation-free per harness rules)
__device__ __half g_xh[(size_t)Mq * HIDq];     // A operand fp16 [M,K] (x, later ctx)
__device__ __half g_wt4[(size_t)4 * HIDq * HIDq];  // W^T fp16 [4][N,K] (q,k,v,p)
__device__ __half g_qh[(size_t)Bq * NHq * Sq * HDq];  // [B,NH,S,HD] (pre-scaled by rsqrt(HID)*log2e)
__device__ __half g_kh[(size_t)Bq * NHq * Sq * HDq];
__device__ __half g_vh[(size_t)Bq * NHq * Sq * HDq];

// ===========================================================================
// PTX helpers (portable tensor ISA: ldmatrix + mma.sync, sm_80+)
// ===========================================================================
__device__ __forceinline__ uint32_t smem_to_u32(const void* p) {
    uint32_t a;
    asm("{ .reg .u64 t; cvta.to.shared.u64 t, %1; cvt.u32.u64 %0, t; }"
        : "=r"(a) : "l"(p));
    return a;
}

#define LDMX4(r, addr) \
    asm volatile("ldmatrix.sync.aligned.m8n8.x4.shared.b16 {%0,%1,%2,%3}, [%4];" \
        : "=r"((r)[0]), "=r"((r)[1]), "=r"((r)[2]), "=r"((r)[3]) : "r"(addr))

#define LDMX2(r, addr) \
    asm volatile("ldmatrix.sync.aligned.m8n8.x2.shared.b16 {%0,%1}, [%2];" \
        : "=r"((r)[0]), "=r"((r)[1]) : "r"(addr))

#define LDMX2T(r, addr) \
    asm volatile("ldmatrix.sync.aligned.m8n8.x2.trans.shared.b16 {%0,%1}, [%2];" \
        : "=r"((r)[0]), "=r"((r)[1]) : "r"(addr))

#define MMA_F16(d, a, b) \
    asm volatile("mma.sync.aligned.m16n8k16.row.col.f32.f16.f16.f32 " \
        "{%0,%1,%2,%3}, {%4,%5,%6,%7}, {%8,%9}, {%0,%1,%2,%3};" \
        : "+f"((d)[0]), "+f"((d)[1]), "+f"((d)[2]), "+f"((d)[3]) \
        : "r"((a)[0]), "r"((a)[1]), "r"((a)[2]), "r"((a)[3]), \
          "r"((b)[0]), "r"((b)[1]))

#define CP_ASYNC16(smem, gmem) \
    asm volatile("cp.async.cg.shared.global [%0], [%1], 16;" \
        :: "r"(smem), "l"(gmem) : "memory")
#define CP_COMMIT()  asm volatile("cp.async.commit_group;" ::: "memory")
#define CP_WAIT(n)   asm volatile("cp.async.wait_group %0;" :: "n"(n) : "memory")

#define LOG2E 1.44269504f

// ===========================================================================
// Merged conversion kernel: grid (32,32,8).
//   z in [0,4): transpose+convert Wz -> g_wt4[z]
//   z in [4,8): convert x fp32 -> fp16 (4096 logical blocks)
// ===========================================================================
__global__ __launch_bounds__(256) void conv_all_kernel(
    const float* __restrict__ x,
    const float* __restrict__ W0, const float* __restrict__ W1,
    const float* __restrict__ W2, const float* __restrict__ W3)
{
    if (blockIdx.z < 4) {
        __shared__ float tile[32][33];
        const float* W = (blockIdx.z == 0) ? W0 : (blockIdx.z == 1) ? W1
                       : (blockIdx.z == 2) ? W2 : W3;
        __half* dst = g_wt4 + (size_t)blockIdx.z * HIDq * HIDq;
        const int bx = blockIdx.x * 32, by = blockIdx.y * 32;
        const int tx = threadIdx.x & 31, ty = threadIdx.x >> 5;  // 32 x 8
#pragma unroll
        for (int i = 0; i < 4; i++)
            tile[ty + i * 8][tx] = W[(size_t)(by + ty + i * 8) * HIDq + bx + tx];
        __syncthreads();
#pragma unroll
        for (int i = 0; i < 4; i++)
            dst[(size_t)(bx + ty + i * 8) * HIDq + by + tx] =
                __float2half(tile[tx][ty + i * 8]);
    } else {
        const size_t bid = (size_t)(blockIdx.z - 4) * 1024 + blockIdx.y * 32 + blockIdx.x;
        const size_t i = (bid * 256 + threadIdx.x) * 8;
        float4 v0 = *(const float4*)(x + i);
        float4 v1 = *(const float4*)(x + i + 4);
        __half2 h0 = __floats2half2_rn(v0.x, v0.y);
        __half2 h1 = __floats2half2_rn(v0.z, v0.w);
        __half2 h2 = __floats2half2_rn(v1.x, v1.y);
        __half2 h3 = __floats2half2_rn(v1.z, v1.w);
        *(uint4*)(g_xh + i) = make_uint4(*(uint32_t*)&h0, *(uint32_t*)&h1,
                                         *(uint32_t*)&h2, *(uint32_t*)&h3);
    }
}

// ===========================================================================
// fp16 mma.sync GEMM core v2: CTA 128x128, 128 threads (4 warps, 2m x 2n),
// warp tile 64x64 (128 B of smem per MMA vs 192 before). 3-stage cp.async,
// KCH=64, row stride 144 B. 2 CTAs/SM (regs ~165/thread < 256 cap).
// ===========================================================================
#define KCH    64
#define GTILE  18432                    // 128 rows x 144 B
#define GSTG   (2 * GTILE)              // A + B per stage
#define GSMEM  (3 * GSTG)               // 110592 B, 3 stages
#define NCH    (HIDq / KCH)             // 16

// QKV merged GEMM: z = blockIdx.z selects weight slot, bias, destination.
__global__ __launch_bounds__(128, 2) void gemm_qkv_kernel(
    const float* __restrict__ b0, const float* __restrict__ b1,
    const float* __restrict__ b2)
{
    extern __shared__ char sm[];
    const uint32_t sb = smem_to_u32(sm);
    const int z = blockIdx.z;
    const __half* Wt = g_wt4 + (size_t)z * HIDq * HIDq;
    const float* bias = (z == 0) ? b0 : (z == 1) ? b1 : b2;
    __half* dst = (z == 0) ? g_qh : (z == 1) ? g_kh : g_vh;

    const int tid = threadIdx.x, lane = tid & 31, wid = tid >> 5;
    const int wm = wid >> 1, wn = wid & 1;             // 2 x 2 warp grid
    const int bm = blockIdx.y * 128, bn = blockIdx.x * 128;

    float acc[4][8][4];
#pragma unroll
    for (int mi = 0; mi < 4; mi++)
#pragma unroll
        for (int ni = 0; ni < 8; ni++)
#pragma unroll
            for (int r = 0; r < 4; r++) acc[mi][ni][r] = 0.f;

    auto issue = [&](int c) {
        const uint32_t base = sb + (uint32_t)(c % 3) * GSTG;
        const int k0 = c * KCH;
#pragma unroll
        for (int t = 0; t < 8; t++) {
            const int id = t * 128 + tid;
            const int row = id >> 3, seg = id & 7;
            const uint32_t so = (uint32_t)row * 144 + seg * 16;
            CP_ASYNC16(base + so,         g_xh + (size_t)(bm + row) * HIDq + k0 + seg * 8);
            CP_ASYNC16(base + GTILE + so, Wt   + (size_t)(bn + row) * HIDq + k0 + seg * 8);
        }
        CP_COMMIT();
    };

    issue(0);
    issue(1);

    for (int c = 0; c < NCH; c++) {
        CP_WAIT(1);
        __syncthreads();

        const uint32_t base = sb + (uint32_t)(c % 3) * GSTG;

#pragma unroll
        for (int kk = 0; kk < KCH; kk += 16) {
            uint32_t bh[8][2];
#pragma unroll
            for (int ni = 0; ni < 8; ni++) {
                const uint32_t baddr = base + GTILE
                    + (uint32_t)(wn * 64 + ni * 8 + (lane & 7)) * 144
                    + (uint32_t)(kk + ((lane >> 3) & 1) * 8) * 2;
                LDMX2(bh[ni], baddr);
            }
#pragma unroll
            for (int mi = 0; mi < 4; mi++) {
                const uint32_t aaddr = base
                    + (uint32_t)(wm * 64 + mi * 16 + (lane & 15)) * 144
                    + (uint32_t)(kk + (lane >> 4) * 8) * 2;
                uint32_t ah[4];
                LDMX4(ah, aaddr);
#pragma unroll
                for (int ni = 0; ni < 8; ni++)
                    MMA_F16(acc[mi][ni], ah, bh[ni]);
            }
        }
        if (c + 2 < NCH) issue(c + 2);
    }

    const int rbase = bm + wm * 64 + (lane >> 2);
    const int cbase = bn + wn * 64 + (lane & 3) * 2;
    // Q pre-scale includes log2(e) so attention scores live in log2 domain.
    const float qs = (z == 0) ? 0.03125f * LOG2E : 1.0f;
#pragma unroll
    for (int mi = 0; mi < 4; mi++) {
#pragma unroll
        for (int ni = 0; ni < 8; ni++) {
            const int col = cbase + ni * 8;
            const float2 b2v = *(const float2*)(bias + col);
#pragma unroll
            for (int half = 0; half < 2; half++) {
                const int row = rbase + mi * 16 + half * 8;
                const float ox = (acc[mi][ni][half * 2 + 0] + b2v.x) * qs;
                const float oy = (acc[mi][ni][half * 2 + 1] + b2v.y) * qs;
                const int b = row >> 10, s = row & 1023;
                const int h = col >> 6,  d = col & 63;
                const size_t off = (((size_t)(b * NHq + h)) * Sq + s) * HDq + d;
                __half2 h2 = __floats2half2_rn(ox, oy);
                *(uint32_t*)(dst + off) = *(uint32_t*)&h2;
            }
        }
    }
}

// Output projection: A = g_xh (ctx), W slot 3, fp32 row-major to d_out.
__global__ __launch_bounds__(128, 2) void gemm_out_kernel(
    const float* __restrict__ bias, float* __restrict__ Cout)
{
    extern __shared__ char sm[];
    const uint32_t sb = smem_to_u32(sm);
    const __half* Wt = g_wt4 + (size_t)3 * HIDq * HIDq;

    const int tid = threadIdx.x, lane = tid & 31, wid = tid >> 5;
    const int wm = wid >> 1, wn = wid & 1;
    const int bm = blockIdx.y * 128, bn = blockIdx.x * 128;

    float acc[4][8][4];
#pragma unroll
    for (int mi = 0; mi < 4; mi++)
#pragma unroll
        for (int ni = 0; ni < 8; ni++)
#pragma unroll
            for (int r = 0; r < 4; r++) acc[mi][ni][r] = 0.f;

    auto issue = [&](int c) {
        const uint32_t base = sb + (uint32_t)(c % 3) * GSTG;
        const int k0 = c * KCH;
#pragma unroll
        for (int t = 0; t < 8; t++) {
            const int id = t * 128 + tid;
            const int row = id >> 3, seg = id & 7;
            const uint32_t so = (uint32_t)row * 144 + seg * 16;
            CP_ASYNC16(base + so,         g_xh + (size_t)(bm + row) * HIDq + k0 + seg * 8);
            CP_ASYNC16(base + GTILE + so, Wt   + (size_t)(bn + row) * HIDq + k0 + seg * 8);
        }
        CP_COMMIT();
    };

    issue(0);
    issue(1);

    for (int c = 0; c < NCH; c++) {
        CP_WAIT(1);
        __syncthreads();

        const uint32_t base = sb + (uint32_t)(c % 3) * GSTG;

#pragma unroll
        for (int kk = 0; kk < KCH; kk += 16) {
            uint32_t bh[8][2];
#pragma unroll
            for (int ni = 0; ni < 8; ni++) {
                const uint32_t baddr = base + GTILE
                    + (uint32_t)(wn * 64 + ni * 8 + (lane & 7)) * 144
                    + (uint32_t)(kk + ((lane >> 3) & 1) * 8) * 2;
                LDMX2(bh[ni], baddr);
            }
#pragma unroll
            for (int mi = 0; mi < 4; mi++) {
                const uint32_t aaddr = base
                    + (uint32_t)(wm * 64 + mi * 16 + (lane & 15)) * 144
                    + (uint32_t)(kk + (lane >> 4) * 8) * 2;
                uint32_t ah[4];
                LDMX4(ah, aaddr);
#pragma unroll
                for (int ni = 0; ni < 8; ni++)
                    MMA_F16(acc[mi][ni], ah, bh[ni]);
            }
        }
        if (c + 2 < NCH) issue(c + 2);
    }

    const int rbase = bm + wm * 64 + (lane >> 2);
    const int cbase = bn + wn * 64 + (lane & 3) * 2;
#pragma unroll
    for (int mi = 0; mi < 4; mi++) {
#pragma unroll
        for (int ni = 0; ni < 8; ni++) {
            const int col = cbase + ni * 8;
            const float2 b2v = *(const float2*)(bias + col);
#pragma unroll
            for (int half = 0; half < 2; half++) {
                const int row = rbase + mi * 16 + half * 8;
                *(float2*)(Cout + (size_t)row * HIDq + col) =
                    make_float2(acc[mi][ni][half * 2 + 0] + b2v.x,
                                acc[mi][ni][half * 2 + 1] + b2v.y);
            }
        }
    }
}

// ===========================================================================
// fp16 flash attention (R15, unchanged): 256 threads = 8 warps, warp owns 16
// query rows; 128-query tile, 64-key stages, 3-stage KV pipeline, log2-domain
// softmax with h2exp2. smem 73.7 KB, 2 CTAs/SM. ctx -> fp16 into g_xh.
// ===========================================================================
#define QTILE  18432                    // 128 rows x 144 B
#define KVTILE 9216                     // 64 rows x 144 B
#define KVSTG  (2 * KVTILE)             // Kh, Vh
#define KVOFF  QTILE
#define ASMEM  (KVOFF + 3 * KVSTG)      // 73728
#define NTK    (Sq / 64)                // 16

__global__ __launch_bounds__(256, 2) void attn_mma_kernel(const float* __restrict__ mask)
{
    extern __shared__ char sm[];
    const uint32_t sb = smem_to_u32(sm);

    const int bh = blockIdx.y;
    const int b = bh >> 4, h = bh & 15;
    const int qbase = blockIdx.x * 128;
    const int tid = threadIdx.x, lane = tid & 31, wid = tid >> 5;
    const int wrow = wid * 16;

    const size_t hb = (size_t)bh * Sq * HDq;
    const __half* Qg = g_qh + hb;
    const __half* KVg[2] = {g_kh + hb, g_vh + hb};

#pragma unroll
    for (int t = 0; t < 4; t++) {
        const int id = t * 256 + tid;
        const int row = id >> 3, seg = id & 7;
        CP_ASYNC16(sb + (uint32_t)row * 144 + seg * 16,
                   Qg + (size_t)(qbase + row) * HDq + seg * 8);
    }

    auto issue_kv = [&](int kt) {
        const uint32_t base = sb + KVOFF + (uint32_t)(kt % 3) * KVSTG;
#pragma unroll
        for (int t = 0; t < 4; t++) {
            const int which = t >> 1;           // 0=Kh, 1=Vh
            const int id = (t & 1) * 256 + tid;
            const int row = id >> 3, seg = id & 7;
            CP_ASYNC16(base + (uint32_t)which * KVTILE + (uint32_t)row * 144 + seg * 16,
                       KVg[which] + (size_t)(kt * 64 + row) * HDq + seg * 8);
        }
        CP_COMMIT();
    };

    issue_kv(0);
    issue_kv(1);

    float m_st[2] = {-1e30f, -1e30f};
    float l_st[2] = {0.f, 0.f};
    float ctx[8][4];
#pragma unroll
    for (int n = 0; n < 8; n++)
#pragma unroll
        for (int r = 0; r < 4; r++) ctx[n][r] = 0.f;

    const int r0 = qbase + wrow + (lane >> 2);
    const float MSCALE = -1e9f * LOG2E;

    for (int kt = 0; kt < NTK; kt++) {
        CP_WAIT(1);
        __syncthreads();

        const uint32_t kvb = sb + KVOFF + (uint32_t)(kt % 3) * KVSTG;

        float accs[8][4];
#pragma unroll
        for (int n = 0; n < 8; n++)
#pragma unroll
            for (int r = 0; r < 4; r++) accs[n][r] = 0.f;

#pragma unroll
        for (int k0 = 0; k0 < 64; k0 += 16) {
            uint32_t ah[4];
            const uint32_t aaddr = sb + (uint32_t)(wrow + (lane & 15)) * 144
                                 + (uint32_t)(k0 + (lane >> 4) * 8) * 2;
            LDMX4(ah, aaddr);
#pragma unroll
            for (int n = 0; n < 8; n++) {
                const uint32_t baddr = kvb + (uint32_t)(n * 8 + (lane & 7)) * 144
                                     + (uint32_t)(k0 + ((lane >> 3) & 1) * 8) * 2;
                uint32_t kb[2];
                LDMX2(kb, baddr);
                MMA_F16(accs[n], ah, kb);
            }
        }

        const float* mrow0 = mask + ((size_t)b * Sq + r0) * Sq + kt * 64 + (lane & 3) * 2;
        const float* mrow1 = mrow0 + 8 * Sq;
#pragma unroll
        for (int n = 0; n < 8; n++) {
            const float2 m0 = *(const float2*)(mrow0 + n * 8);
            const float2 m1 = *(const float2*)(mrow1 + n * 8);
            accs[n][0] = fmaf(m0.x, MSCALE, accs[n][0]);
            accs[n][1] = fmaf(m0.y, MSCALE, accs[n][1]);
            accs[n][2] = fmaf(m1.x, MSCALE, accs[n][2]);
            accs[n][3] = fmaf(m1.y, MSCALE, accs[n][3]);
        }

        float mx0 = -1e30f, mx1 = -1e30f;
#pragma unroll
        for (int n = 0; n < 8; n++) {
            mx0 = fmaxf(mx0, fmaxf(accs[n][0], accs[n][1]));
            mx1 = fmaxf(mx1, fmaxf(accs[n][2], accs[n][3]));
        }
        mx0 = fmaxf(mx0, __shfl_xor_sync(0xffffffffu, mx0, 1));
        mx0 = fmaxf(mx0, __shfl_xor_sync(0xffffffffu, mx0, 2));
        mx1 = fmaxf(mx1, __shfl_xor_sync(0xffffffffu, mx1, 1));
        mx1 = fmaxf(mx1, __shfl_xor_sync(0xffffffffu, mx1, 2));

        const float mn0 = fmaxf(m_st[0], mx0);
        const float mn1 = fmaxf(m_st[1], mx1);
        const float al0 = exp2f(m_st[0] - mn0);
        const float al1 = exp2f(m_st[1] - mn1);
        m_st[0] = mn0; m_st[1] = mn1;

#pragma unroll
        for (int n = 0; n < 8; n++) {
            ctx[n][0] *= al0; ctx[n][1] *= al0;
            ctx[n][2] *= al1; ctx[n][3] *= al1;
        }

        const uint32_t vbase = kvb + KVTILE;
        __half2 sh0 = __floats2half2_rn(0.f, 0.f);
        __half2 sh1 = sh0;
#pragma unroll
        for (int kk2 = 0; kk2 < 4; kk2++) {
            __half2 t0 = __floats2half2_rn(accs[2 * kk2][0] - mn0,     accs[2 * kk2][1] - mn0);
            __half2 t1 = __floats2half2_rn(accs[2 * kk2][2] - mn1,     accs[2 * kk2][3] - mn1);
            __half2 t2 = __floats2half2_rn(accs[2 * kk2 + 1][0] - mn0, accs[2 * kk2 + 1][1] - mn0);
            __half2 t3 = __floats2half2_rn(accs[2 * kk2 + 1][2] - mn1, accs[2 * kk2 + 1][3] - mn1);
            __half2 p0 = h2exp2(t0);
            __half2 p1 = h2exp2(t1);
            __half2 p2 = h2exp2(t2);
            __half2 p3 = h2exp2(t3);
            sh0 = __hadd2(sh0, __hadd2(p0, p2));
            sh1 = __hadd2(sh1, __hadd2(p1, p3));
            uint32_t pf[4];
            pf[0] = *(uint32_t*)&p0; pf[1] = *(uint32_t*)&p1;
            pf[2] = *(uint32_t*)&p2; pf[3] = *(uint32_t*)&p3;
#pragma unroll
            for (int n = 0; n < 8; n++) {
                const uint32_t vaddr = vbase + (uint32_t)(kk2 * 16 + (lane & 15)) * 144
                                     + (uint32_t)n * 16;
                uint32_t vh[2];
                LDMX2T(vh, vaddr);
                MMA_F16(ctx[n], pf, vh);
            }
        }

        float2 s0f = __half22float2(sh0);
        float2 s1f = __half22float2(sh1);
        float sum0 = s0f.x + s0f.y;
        float sum1 = s1f.x + s1f.y;
        sum0 += __shfl_xor_sync(0xffffffffu, sum0, 1);
        sum0 += __shfl_xor_sync(0xffffffffu, sum0, 2);
        sum1 += __shfl_xor_sync(0xffffffffu, sum1, 1);
        sum1 += __shfl_xor_sync(0xffffffffu, sum1, 2);
        l_st[0] = l_st[0] * al0 + sum0;
        l_st[1] = l_st[1] * al1 + sum1;

        if (kt + 2 < NTK) issue_kv(kt + 2);
    }

    const float inv0 = 1.0f / l_st[0];
    const float inv1 = 1.0f / l_st[1];
    const int cb = h * HDq + (lane & 3) * 2;
#pragma unroll
    for (int n = 0; n < 8; n++) {
        const int col = cb + n * 8;
        const size_t off0 = ((size_t)(b * Sq + r0)) * HIDq + col;
        const size_t off1 = ((size_t)(b * Sq + r0 + 8)) * HIDq + col;
        __half2 h0 = __floats2half2_rn(ctx[n][0] * inv0, ctx[n][1] * inv0);
        __half2 h1 = __floats2half2_rn(ctx[n][2] * inv1, ctx[n][3] * inv1);
        *(uint32_t*)(g_xh + off0) = *(uint32_t*)&h0;
        *(uint32_t*)(g_xh + off1) = *(uint32_t*)&h1;
    }
}

// ---------------------------------------------------------------------------
extern "C" void kernel_launch(void* const* d_in, const int* in_sizes, int n_in,
                              void* d_out, int out_size)
{
    (void)in_sizes; (void)n_in; (void)out_size;
    const float* x   = (const float*)d_in[0];
    const float* msk = (const float*)d_in[1];
    const float* Wq  = (const float*)d_in[2];
    const float* bq  = (const float*)d_in[3];
    const float* Wk  = (const float*)d_in[4];
    const float* bk  = (const float*)d_in[5];
    const float* Wv  = (const float*)d_in[6];
    const float* bv  = (const float*)d_in[7];
    const float* Wp  = (const float*)d_in[8];
    const float* bp  = (const float*)d_in[9];
    float* out = (float*)d_out;

    cudaFuncSetAttribute(gemm_qkv_kernel, cudaFuncAttributeMaxDynamicSharedMemorySize, GSMEM);
    cudaFuncSetAttribute(gemm_out_kernel, cudaFuncAttributeMaxDynamicSharedMemorySize, GSMEM);
    cudaFuncSetAttribute(attn_mma_kernel, cudaFuncAttributeMaxDynamicSharedMemorySize, ASMEM);

    conv_all_kernel<<<dim3(32, 32, 8), 256>>>(x, Wq, Wk, Wv, Wp);

    gemm_qkv_kernel<<<dim3(HIDq / 128, Mq / 128, 3), 128, GSMEM>>>(bq, bk, bv);

    attn_mma_kernel<<<dim3(Sq / 128, Bq * NHq), 256, ASMEM>>>(msk);

    gemm_out_kernel<<<dim3(HIDq / 128, Mq / 128), 128, GSMEM>>>(bp, out);
}